// round 1
// baseline (speedup 1.0000x reference)
#include <cuda_runtime.h>

#define NT 256
#define STEPS 15
#define SPEED 5.0f
#define NCOLS_IN 18
#define NCOLS_OUT 178

__global__ void __launch_bounds__(NT) prog_kernel(
    const float* __restrict__ x,
    const float* __restrict__ c1w, const float* __restrict__ c1b,
    const float* __restrict__ c2w, const float* __restrict__ c2b,
    const float* __restrict__ l1w, const float* __restrict__ l1b,
    const float* __restrict__ l2w, const float* __restrict__ l2b,
    float* __restrict__ out, int n)
{
    // Weights staged in SMEM, laid out for wide broadcast loads:
    //  s_l1wt: l1w transposed to (32,4) -> one LDS.128 per j
    //  s_l2w : l2w rows padded to stride 8 -> LDS.128 + LDS.32 per j
    __shared__ float s_l1wt[128];
    __shared__ float s_l2w[256];
    __shared__ float s_l1b[32];
    __shared__ float s_l2b[8];
    __shared__ float s_c[8];

    const int t = threadIdx.x;
    for (int u = t; u < 128; u += NT) {            // l1w[i*32+j] -> [j*4+i]
        int i = u >> 5, j = u & 31;
        s_l1wt[j * 4 + i] = l1w[u];
    }
    for (int u = t; u < 160; u += NT) {            // l2w[j*5+k] -> [j*8+k]
        int j = u / 5, k = u - 5 * j;
        s_l2w[j * 8 + k] = l2w[u];
    }
    for (int u = t; u < 32; u += NT) s_l1b[u] = l1b[u];
    for (int u = t; u < 5;  u += NT) s_l2b[u] = l2b[u];
    if (t == 0) {
        s_c[0] = c1w[0]; s_c[1] = c1w[1]; s_c[2] = c1b[0];
        s_c[3] = c2w[0]; s_c[4] = c2w[1]; s_c[5] = c2b[0];
    }
    __syncthreads();

    const int row = blockIdx.x * NT + t;
    if (row >= n) return;

    const float c1w0 = s_c[0], c1w1 = s_c[1], c1b0 = s_c[2];
    const float c2w0 = s_c[3], c2w1 = s_c[4], c2b0 = s_c[5];

    // ---- load state row (18 floats, 8B-aligned) ----
    const float* xr = x + (long long)row * NCOLS_IN;
    float2 v0 = *(const float2*)(xr + 0);
    float2 v1 = *(const float2*)(xr + 2);
    float2 v2 = *(const float2*)(xr + 4);
    float2 v3 = *(const float2*)(xr + 6);
    float2 v4 = *(const float2*)(xr + 8);
    float2 v5 = *(const float2*)(xr + 10);
    float2 v6 = *(const float2*)(xr + 12);
    float2 v7 = *(const float2*)(xr + 14);
    float2 v8 = *(const float2*)(xr + 16);
    float s0 = v0.x, s1 = v0.y, s2 = v1.x, s3 = v1.y;
    float s4 = v2.x, s5 = v2.y, s6 = v3.x, s7 = v3.y;
    float s8 = v4.x, s9 = v4.y, s10 = v5.x, s11 = v5.y;
    float s12 = v6.x, s13 = v6.y, s14 = v7.x, s15 = v7.y;
    float s16 = v8.x, s17 = v8.y;
    (void)s11; (void)s12; (void)s13; (void)s14; (void)s15; (void)s16;

    // initial distance
    {
        float d13 = s1 - s3, d24 = s2 - s4;
        s10 = d13 * d13 + d24 * d24;
    }

    float* orow = out + (long long)row * NCOLS_OUT;

    // traj0 = s[10,1,2,3,4,5,6,7,8,17] at columns [18,28)
    {
        float* o = orow + 18;
        *(float2*)(o + 0) = make_float2(s10, s1);
        *(float2*)(o + 2) = make_float2(s2, s3);
        *(float2*)(o + 4) = make_float2(s4, s5);
        *(float2*)(o + 6) = make_float2(s6, s7);
        *(float2*)(o + 8) = make_float2(s8, s17);
    }

    #pragma unroll 1
    for (int step = 0; step < STEPS; step++) {
        // feat = s[1,2,3,4,9,17]
        const float f0 = s1, f1 = s2, f2 = s3, f3 = s4, f4 = s9, f5 = s17;

        float h10 = fmaxf(fmaf(c1w1, f1, fmaf(c1w0, f0, c1b0)), 0.0f);
        float h11 = fmaxf(fmaf(c1w1, f2, fmaf(c1w0, f1, c1b0)), 0.0f);
        float h12 = fmaxf(fmaf(c1w1, f3, fmaf(c1w0, f2, c1b0)), 0.0f);
        float h13 = fmaxf(fmaf(c1w1, f4, fmaf(c1w0, f3, c1b0)), 0.0f);
        float h14 = fmaxf(fmaf(c1w1, f5, fmaf(c1w0, f4, c1b0)), 0.0f);

        float h20 = fmaxf(fmaf(c2w1, h11, fmaf(c2w0, h10, c2b0)), 0.0f);
        float h21 = fmaxf(fmaf(c2w1, h12, fmaf(c2w0, h11, c2b0)), 0.0f);
        float h22 = fmaxf(fmaf(c2w1, h13, fmaf(c2w0, h12, c2b0)), 0.0f);
        float h23 = fmaxf(fmaf(c2w1, h14, fmaf(c2w0, h13, c2b0)), 0.0f);

        float p0 = s_l2b[0], p1 = s_l2b[1], p2 = s_l2b[2], p3 = s_l2b[3], p4 = s_l2b[4];

        #pragma unroll
        for (int j = 0; j < 32; j++) {
            const float4 w1 = *(const float4*)(s_l1wt + 4 * j);
            float h3 = fmaf(h23, w1.w, fmaf(h22, w1.z, fmaf(h21, w1.y, fmaf(h20, w1.x, s_l1b[j]))));
            h3 = fmaxf(h3, 0.0f);
            const float4 w2 = *(const float4*)(s_l2w + 8 * j);
            const float w24 = s_l2w[8 * j + 4];
            p0 = fmaf(h3, w2.x, p0);
            p1 = fmaf(h3, w2.y, p1);
            p2 = fmaf(h3, w2.z, p2);
            p3 = fmaf(h3, w2.w, p3);
            p4 = fmaf(h3, w24, p4);
        }

        // sigmoid, full precision
        p0 = 1.0f / (1.0f + expf(-p0));
        p1 = 1.0f / (1.0f + expf(-p1));
        p2 = 1.0f / (1.0f + expf(-p2));
        p3 = 1.0f / (1.0f + expf(-p3));
        p4 = 1.0f / (1.0f + expf(-p4));

        s5 = p0; s6 = p1; s7 = p2; s8 = p3; s17 = p4;

        const float a = p1 - p0, b = p2 - p0, c = p3 - p0;
        const float d = p2 - p1, e = p3 - p1, f = p3 - p2;
        s11 = a; s12 = b; s13 = c; s14 = d; s15 = e; s16 = f;

        const float dx_c = (c <= 0.0f) ? 0.0f : SPEED;
        const float st_c = (c <= 0.0f) ? 0.0f : 3.0f;
        const float dx_f = (f <= 0.0f) ? 0.0f : SPEED;
        const float st_f = (f <= 0.0f) ? 2.0f : 3.0f;
        const float dx_e = (e <= 0.0f) ? -SPEED : SPEED;
        const float st_e = (e <= 0.0f) ? 1.0f : 3.0f;
        const float dx_b = (b <= 0.0f) ? dx_c : dx_f;
        const float st_b = (b <= 0.0f) ? st_c : st_f;
        const float dx_d = (d <= 0.0f) ? dx_e : dx_f;
        const float st_d = (d <= 0.0f) ? st_e : st_f;
        const float dx   = (a <= 0.0f) ? dx_b : dx_d;
        const float st   = (a <= 0.0f) ? st_b : st_d;

        s1 += dx;
        s9 = st;
        s2 += SPEED;
        s3 += SPEED;
        s0 += 1.0f;
        {
            float d13 = s1 - s3, d24 = s2 - s4;
            s10 = d13 * d13 + d24 * d24;
        }

        // record traj: columns [18 + 10*(step+1), +10)
        float* o = orow + 18 + 10 * (step + 1);
        *(float2*)(o + 0) = make_float2(s10, s1);
        *(float2*)(o + 2) = make_float2(s2, s3);
        *(float2*)(o + 4) = make_float2(s4, s5);
        *(float2*)(o + 6) = make_float2(s6, s7);
        *(float2*)(o + 8) = make_float2(s8, s17);
    }

    // final state -> columns [0,18)
    *(float2*)(orow + 0)  = make_float2(s0, s1);
    *(float2*)(orow + 2)  = make_float2(s2, s3);
    *(float2*)(orow + 4)  = make_float2(s4, s5);
    *(float2*)(orow + 6)  = make_float2(s6, s7);
    *(float2*)(orow + 8)  = make_float2(s8, s9);
    *(float2*)(orow + 10) = make_float2(s10, s11);
    *(float2*)(orow + 12) = make_float2(s12, s13);
    *(float2*)(orow + 14) = make_float2(s14, s15);
    *(float2*)(orow + 16) = make_float2(s16, s17);
}

extern "C" void kernel_launch(void* const* d_in, const int* in_sizes, int n_in,
                              void* d_out, int out_size)
{
    const float* x   = (const float*)d_in[0];
    const float* c1w = (const float*)d_in[1];
    const float* c1b = (const float*)d_in[2];
    const float* c2w = (const float*)d_in[3];
    const float* c2b = (const float*)d_in[4];
    const float* l1w = (const float*)d_in[5];
    const float* l1b = (const float*)d_in[6];
    const float* l2w = (const float*)d_in[7];
    const float* l2b = (const float*)d_in[8];
    float* out = (float*)d_out;

    const int n = in_sizes[0] / NCOLS_IN;
    const int blocks = (n + NT - 1) / NT;
    prog_kernel<<<blocks, NT>>>(x, c1w, c1b, c2w, c2b, l1w, l1b, l2w, l2b, out, n);
}